// round 3
// baseline (speedup 1.0000x reference)
#include <cuda_runtime.h>
#include <math.h>

#define NN  50000
#define EE  1250000
#define DIMM 64
#define HHH 16

typedef unsigned long long ull;

// Scratch (device globals; no runtime allocation). float4 layout: [node][head] = 16B
__device__ float4 g_q[NN * HHH];
__device__ float4 g_k[NN * HHH];
__device__ float4 g_v[NN * HHH];
__device__ float  g_dot[NN * DIMM];
__device__ float4 g_agg[NN * HHH];

// ---------------- packed f32x2 helpers (SASS FFMA2 / FADD2) -----------------
__device__ __forceinline__ void ffma2(ull &acc, ull a, ull b) {
    asm("fma.rn.f32x2 %0, %1, %2, %0;" : "+l"(acc) : "l"(a), "l"(b));
}
__device__ __forceinline__ void fadd2(ull &acc, ull a) {
    asm("add.rn.f32x2 %0, %0, %1;" : "+l"(acc) : "l"(a));
}
__device__ __forceinline__ ull pack2(float a, float b) {
    ull r; asm("mov.b64 %0, {%1,%2};" : "=l"(r) : "f"(a), "f"(b)); return r;
}
__device__ __forceinline__ float sum2(ull v) {
    float a, b; asm("mov.b64 {%0,%1}, %2;" : "=f"(a), "=f"(b) : "l"(v));
    return a + b;
}

// ---------------------------------------------------------------------------
// K_A: fused node-side pre-kernel, 256 threads/block.
//   blocks [0, VEC_B)                : iv = node_vec @ vec_w ; g_dot
//   blocks [VEC_B, VEC_B+QKV_B)     : LayerNorm + QKV projection
//   blocks [VEC_B+QKV_B, total)     : zero g_agg
// ---------------------------------------------------------------------------
#define VEC_B  1024
#define QKV_B  2048
#define ZERO_B 512
#define NODE_ITERS 25   // ceil(50000/2048) for both vec (1024 blk * 2 nodes) and qkv

__global__ void __launch_bounds__(256) node_kernel(
    const float* __restrict__ node_feat,
    const float* __restrict__ node_vec,
    const float* __restrict__ ln_g,  const float* __restrict__ ln_b,
    const float* __restrict__ qkv_w, const float* __restrict__ qkv_b,
    const float* __restrict__ vec_w)
{
    const int t   = threadIdx.x;
    const int blk = blockIdx.x;

    if (blk < VEC_B) {
        // ---------------- vec path: 2 nodes per iteration ----------------
        __shared__ __align__(16) float s_nv[2][192];
        __shared__ __align__(16) float s_iv[2][3][128];
        const int sub = t >> 7;        // 0/1 : which node of the pair
        const int tc  = t & 127;       // output column

        ull wc[32];
#pragma unroll
        for (int k = 0; k < 32; k++)
            wc[k] = pack2(vec_w[(2 * k) * 128 + tc], vec_w[(2 * k + 1) * 128 + tc]);

        for (int it = 0; it < NODE_ITERS; it++) {
            const int n = blk * 2 + sub + it * (VEC_B * 2);
            const bool ok = (n < NN);
            if (ok && tc < 96) {
                s_nv[sub][tc]      = node_vec[n * 192 + tc];
                s_nv[sub][tc + 96] = node_vec[n * 192 + tc + 96];
            }
            __syncthreads();
            if (ok) {
                const ull* nv2 = (const ull*)s_nv[sub];
#pragma unroll
                for (int a = 0; a < 3; a++) {
                    ull acc0 = 0, acc1 = 0;
#pragma unroll
                    for (int k = 0; k < 32; k += 2) {
                        ffma2(acc0, nv2[a * 32 + k],     wc[k]);
                        ffma2(acc1, nv2[a * 32 + k + 1], wc[k + 1]);
                    }
                    fadd2(acc0, acc1);
                    s_iv[sub][a][tc] = sum2(acc0);
                }
            }
            __syncthreads();
            if (ok && tc < 64) {
                float d = 0.f;
#pragma unroll
                for (int a = 0; a < 3; a++)
                    d += s_iv[sub][a][tc] * s_iv[sub][a][64 + tc];
                g_dot[n * 64 + tc] = d;
            }
            __syncthreads();
        }
    } else if (blk < VEC_B + QKV_B) {
        // ---------------- qkv path: 1 node per iteration, cols 0..191 ------
        __shared__ __align__(16) float s_x[64];
        __shared__ __align__(16) float s_xn[64];
        const int b = blk - VEC_B;

        ull wc[32];
        float bc = 0.f;
        if (t < 192) {
#pragma unroll
            for (int k = 0; k < 32; k++)
                wc[k] = pack2(qkv_w[(2 * k) * 192 + t], qkv_w[(2 * k + 1) * 192 + t]);
            bc = qkv_b[t];
        }
        const float gg = (t < 64) ? ln_g[t] : 0.f;
        const float bb = (t < 64) ? ln_b[t] : 0.f;
        const int h = t / 12;
        const int r = t % 12;

        for (int it = 0; it < NODE_ITERS; it++) {
            const int n = b + it * QKV_B;
            const bool ok = (n < NN);
            if (ok && t < 64) s_x[t] = node_feat[n * 64 + t];
            __syncthreads();
            if (ok && t < 64) {
                const ull* x2 = (const ull*)s_x;
                ull s = 0, s2 = 0;
#pragma unroll
                for (int k = 0; k < 32; k++) {
                    ull xv = x2[k];
                    fadd2(s, xv);
                    ffma2(s2, xv, xv);
                }
                const float mu   = sum2(s) * (1.f / 64.f);
                const float var  = sum2(s2) * (1.f / 64.f) - mu * mu;
                const float rstd = rsqrtf(var + 1e-5f);
                s_xn[t] = (s_x[t] - mu) * rstd * gg + bb;
            }
            __syncthreads();
            if (ok && t < 192) {
                const ull* xn2 = (const ull*)s_xn;
                ull acc0 = 0, acc1 = 0;
#pragma unroll
                for (int k = 0; k < 32; k += 2) {
                    ffma2(acc0, xn2[k],     wc[k]);
                    ffma2(acc1, xn2[k + 1], wc[k + 1]);
                }
                fadd2(acc0, acc1);
                const float res = sum2(acc0) + bc;

                float* base;
                int    d;
                if (r < 4)      { base = (float*)g_q; d = r; }
                else if (r < 8) { base = (float*)g_k; d = r - 4; }
                else            { base = (float*)g_v; d = r - 8; }
                base[(n * 16 + h) * 4 + d] = res;
            }
            __syncthreads();
        }
    } else {
        // ---------------- zero path ----------------
        const int b = blk - VEC_B - QKV_B;
        const float4 z = make_float4(0.f, 0.f, 0.f, 0.f);
        for (int i = b * 256 + t; i < NN * HHH; i += ZERO_B * 256)
            g_agg[i] = z;
    }
}

// ---------------------------------------------------------------------------
// K3: edge phase. One thread per (edge, head).
// Streaming inputs bypass L1 (__ldcs); gather tables use L1 (__ldg).
// ---------------------------------------------------------------------------
__global__ void __launch_bounds__(256) edge_kernel(
    const float4* __restrict__ edge_feat,
    const float*  __restrict__ radial,
    const int*    __restrict__ row,
    const int*    __restrict__ col)
{
    const int gid = blockIdx.x * blockDim.x + threadIdx.x;
    if (gid >= EE * HHH) return;
    const int e = gid >> 4;
    const int h = gid & 15;

    const int r = __ldcs(&row[e]);
    const int c = __ldcs(&col[e]);

    const float4 qv = __ldg(&g_q[r * 16 + h]);
    const float4 kv = __ldg(&g_k[c * 16 + h]);
    const float dot = qv.x * kv.x + qv.y * kv.y + qv.z * kv.z + qv.w * kv.w;

    // exact GELU: 0.5*x*(1+erf(x/sqrt(2)))
    const float attn = 0.5f * dot * (1.f + erff(dot * 0.70710678118654752f))
                     * __ldcs(&radial[e]);

    const float4 vv = __ldg(&g_v[c * 16 + h]);
    const float4 ef = __ldcs(&edge_feat[e * 16 + h]);

    float* agg = (float*)&g_agg[r * 16 + h];
    atomicAdd(agg + 0, vv.x * ef.x * attn);
    atomicAdd(agg + 1, vv.y * ef.y * attn);
    atomicAdd(agg + 2, vv.z * ef.z * attn);
    atomicAdd(agg + 3, vv.w * ef.w * attn);
}

// ---------------------------------------------------------------------------
// K4: out = agg @ out_w + out_b ; result = input_dot * out[:, :64] + out[:, 64:]
// ---------------------------------------------------------------------------
__global__ void __launch_bounds__(128) out_kernel(
    const float* __restrict__ out_w,
    const float* __restrict__ out_b,
    float* __restrict__ out)
{
    __shared__ __align__(16) float s_a[64];
    __shared__ __align__(16) float s_o[128];
    const int t = threadIdx.x;

    ull wc[32];
#pragma unroll
    for (int k = 0; k < 32; k++)
        wc[k] = pack2(out_w[(2 * k) * 128 + t], out_w[(2 * k + 1) * 128 + t]);
    const float bc = out_b[t];

    const float* agg = (const float*)g_agg;
    for (int it = 0; it < NODE_ITERS; it++) {
        const int n = blockIdx.x + it * 2048;
        const bool ok = (n < NN);
        if (ok && t < 64) s_a[t] = agg[n * 64 + t];
        __syncthreads();
        if (ok) {
            const ull* a2 = (const ull*)s_a;
            ull acc0 = 0, acc1 = 0;
#pragma unroll
            for (int k = 0; k < 32; k += 2) {
                ffma2(acc0, a2[k],     wc[k]);
                ffma2(acc1, a2[k + 1], wc[k + 1]);
            }
            fadd2(acc0, acc1);
            s_o[t] = sum2(acc0) + bc;
        }
        __syncthreads();
        if (ok && t < 64)
            out[n * 64 + t] = g_dot[n * 64 + t] * s_o[t] + s_o[64 + t];
        __syncthreads();
    }
}

// ---------------------------------------------------------------------------
extern "C" void kernel_launch(void* const* d_in, const int* in_sizes, int n_in,
                              void* d_out, int out_size)
{
    const float* node_feat = (const float*)d_in[0];
    const float* edge_feat = (const float*)d_in[1];
    const float* node_vec  = (const float*)d_in[2];
    const float* radial    = (const float*)d_in[3];
    const float* ln_g      = (const float*)d_in[4];
    const float* ln_b      = (const float*)d_in[5];
    const float* qkv_w     = (const float*)d_in[6];
    const float* qkv_b     = (const float*)d_in[7];
    const float* vec_w     = (const float*)d_in[8];
    const float* out_w     = (const float*)d_in[9];
    const float* out_b     = (const float*)d_in[10];
    const int*   row       = (const int*)d_in[11];
    const int*   col       = (const int*)d_in[12];
    float*       out       = (float*)d_out;

    node_kernel<<<VEC_B + QKV_B + ZERO_B, 256>>>(
        node_feat, node_vec, ln_g, ln_b, qkv_w, qkv_b, vec_w);
    edge_kernel<<<(EE * HHH + 255) / 256, 256>>>(
        (const float4*)edge_feat, radial, row, col);
    out_kernel<<<2048, 128>>>(out_w, out_b, out);
}

// round 5
// speedup vs baseline: 1.2654x; 1.2654x over previous
#include <cuda_runtime.h>
#include <math.h>

#define NN  50000
#define EE  1250000
#define DIMM 64
#define HHH 16

typedef unsigned long long ull;

// Scratch (device globals). float4 layout: [node][head] = 16B
__device__ float4 g_q[NN * HHH];
__device__ float4 g_k[NN * HHH];
__device__ float4 g_v[NN * HHH];
__device__ float  g_dot[NN * DIMM];
__device__ float4 g_agg[NN * HHH];

// ---------------- packed f32x2 helpers (SASS FFMA2 / FADD2) -----------------
__device__ __forceinline__ void ffma2(ull &acc, ull a, ull b) {
    asm("fma.rn.f32x2 %0, %1, %2, %0;" : "+l"(acc) : "l"(a), "l"(b));
}
__device__ __forceinline__ ull pack2(float a, float b) {
    ull r; asm("mov.b64 %0, {%1,%2};" : "=l"(r) : "f"(a), "f"(b)); return r;
}
__device__ __forceinline__ float sum2(ull v) {
    float a, b; asm("mov.b64 {%0,%1}, %2;" : "=f"(a), "=f"(b) : "l"(v));
    return a + b;
}

// ---------------------------------------------------------------------------
// K1: LayerNorm + QKV. 192 threads (one per output col), 8 nodes per iter.
// grid 625 x 10 iters x 8 nodes = 50000 exactly.
// ---------------------------------------------------------------------------
#define QKV_GRID 625
#define QKV_IT   10

__global__ void __launch_bounds__(192) qkv_kernel(
    const float* __restrict__ node_feat,
    const float* __restrict__ ln_g,  const float* __restrict__ ln_b,
    const float* __restrict__ qkv_w, const float* __restrict__ qkv_b)
{
    __shared__ __align__(16) float s_x [8][64];
    __shared__ __align__(16) float s_xn[8][64];
    __shared__ float s_g[64], s_b[64];
    __shared__ float s_mu[8], s_rs[8];
    const int t = threadIdx.x;  // 0..191

    ull wc[32];
#pragma unroll
    for (int k = 0; k < 32; k++)
        wc[k] = pack2(qkv_w[(2 * k) * 192 + t], qkv_w[(2 * k + 1) * 192 + t]);
    const float bc = qkv_b[t];
    if (t < 64) { s_g[t] = ln_g[t]; s_b[t] = ln_b[t]; }

    const int h = t / 12;
    const int r = t % 12;
    float* wbase;
    int    wd;
    if (r < 4)      { wbase = (float*)g_q; wd = r; }
    else if (r < 8) { wbase = (float*)g_k; wd = r - 4; }
    else            { wbase = (float*)g_v; wd = r - 8; }
    __syncthreads();

    for (int it = 0; it < QKV_IT; it++) {
        const int n0 = (blockIdx.x + it * QKV_GRID) * 8;

        // load 8 nodes x 64 feats
        for (int i = t; i < 512; i += 192)
            ((float*)s_x)[i] = node_feat[n0 * 64 + i];
        __syncthreads();

        // LN stats: 16 lanes per node (threads 0..127)
        if (t < 128) {
            const int nd = t >> 4, l = t & 15;
            const float4 v = *(const float4*)&s_x[nd][l * 4];
            float s  = v.x + v.y + v.z + v.w;
            float s2 = v.x * v.x + v.y * v.y + v.z * v.z + v.w * v.w;
#pragma unroll
            for (int o = 8; o >= 1; o >>= 1) {
                s  += __shfl_xor_sync(0xffffffffu, s,  o);
                s2 += __shfl_xor_sync(0xffffffffu, s2, o);
            }
            if (l == 0) {
                const float mu  = s * (1.f / 64.f);
                const float var = s2 * (1.f / 64.f) - mu * mu;
                s_mu[nd] = mu;
                s_rs[nd] = rsqrtf(var + 1e-5f);
            }
        }
        __syncthreads();

        // normalize
        for (int i = t; i < 512; i += 192) {
            const int nd = i >> 6, k = i & 63;
            ((float*)s_xn)[i] = (((float*)s_x)[i] - s_mu[nd]) * s_rs[nd] * s_g[k] + s_b[k];
        }
        __syncthreads();

        // GEMM: 8 independent accumulator chains per thread
        ull acc[8];
#pragma unroll
        for (int nd = 0; nd < 8; nd++) acc[nd] = 0;
        const ull* xn2 = (const ull*)s_xn;
#pragma unroll
        for (int k = 0; k < 32; k++) {
            const ull w = wc[k];
#pragma unroll
            for (int nd = 0; nd < 8; nd++)
                ffma2(acc[nd], xn2[nd * 32 + k], w);
        }
#pragma unroll
        for (int nd = 0; nd < 8; nd++)
            wbase[((n0 + nd) * 16 + h) * 4 + wd] = sum2(acc[nd]) + bc;
        __syncthreads();
    }
}

// ---------------------------------------------------------------------------
// K2: iv = node_vec @ vec_w ; input_dot. 128 threads, 4 nodes/iter.
// grid 625 x 20 x 4 = 50000 exactly.
// ---------------------------------------------------------------------------
#define VEC_GRID 625
#define VEC_IT   20

__global__ void __launch_bounds__(128) vec_kernel(
    const float* __restrict__ node_vec,
    const float* __restrict__ vec_w)
{
    __shared__ __align__(16) float s_nv[4][192];
    __shared__ __align__(16) float s_iv[4][3][128];
    const int t = threadIdx.x;  // 0..127

    ull wc[32];
#pragma unroll
    for (int k = 0; k < 32; k++)
        wc[k] = pack2(vec_w[(2 * k) * 128 + t], vec_w[(2 * k + 1) * 128 + t]);

    for (int it = 0; it < VEC_IT; it++) {
        const int n0 = (blockIdx.x + it * VEC_GRID) * 4;

        for (int i = t; i < 768; i += 128)
            ((float*)s_nv)[i] = node_vec[n0 * 192 + i];
        __syncthreads();

        // 12 independent chains (4 nodes x 3 vector components)
        ull acc[12];
#pragma unroll
        for (int c = 0; c < 12; c++) acc[c] = 0;
        const ull* nv2 = (const ull*)s_nv;
#pragma unroll
        for (int k = 0; k < 32; k++) {
            const ull w = wc[k];
#pragma unroll
            for (int c = 0; c < 12; c++)
                ffma2(acc[c], nv2[c * 32 + k], w);   // c = nd*3 + a, contiguous
        }
#pragma unroll
        for (int nd = 0; nd < 4; nd++)
#pragma unroll
            for (int a = 0; a < 3; a++)
                s_iv[nd][a][t] = sum2(acc[nd * 3 + a]);
        __syncthreads();

        if (t < 64) {
#pragma unroll
            for (int nd = 0; nd < 4; nd++) {
                float d = 0.f;
#pragma unroll
                for (int a = 0; a < 3; a++)
                    d += s_iv[nd][a][t] * s_iv[nd][a][64 + t];
                g_dot[(n0 + nd) * 64 + t] = d;
            }
        }
        __syncthreads();
    }
}

// ---------------------------------------------------------------------------
// Kz: zero the aggregation buffer
// ---------------------------------------------------------------------------
__global__ void zero_kernel()
{
    const int i = blockIdx.x * blockDim.x + threadIdx.x;
    if (i < NN * HHH) g_agg[i] = make_float4(0.f, 0.f, 0.f, 0.f);
}

// ---------------------------------------------------------------------------
// K3: edge phase. One thread per (edge, head). Vector atomics (red.v4.f32).
// ---------------------------------------------------------------------------
__global__ void __launch_bounds__(256) edge_kernel(
    const float4* __restrict__ edge_feat,
    const float*  __restrict__ radial,
    const int*    __restrict__ row,
    const int*    __restrict__ col)
{
    const int gid = blockIdx.x * blockDim.x + threadIdx.x;
    if (gid >= EE * HHH) return;
    const int e = gid >> 4;
    const int h = gid & 15;

    const int r = __ldg(&row[e]);
    const int c = __ldg(&col[e]);

    const float4 qv = __ldg(&g_q[r * 16 + h]);
    const float4 kv = __ldg(&g_k[c * 16 + h]);
    const float dot = qv.x * kv.x + qv.y * kv.y + qv.z * kv.z + qv.w * kv.w;

    // exact GELU: 0.5*x*(1+erf(x/sqrt(2)))
    const float attn = 0.5f * dot * (1.f + erff(dot * 0.70710678118654752f))
                     * __ldg(&radial[e]);

    const float4 vv = __ldg(&g_v[c * 16 + h]);
    const float4 ef = __ldcs(&edge_feat[e * 16 + h]);

    float4* agg = &g_agg[r * 16 + h];
    asm volatile("red.global.add.v4.f32 [%0], {%1, %2, %3, %4};"
                 :: "l"(agg),
                    "f"(vv.x * ef.x * attn), "f"(vv.y * ef.y * attn),
                    "f"(vv.z * ef.z * attn), "f"(vv.w * ef.w * attn)
                 : "memory");
}

// ---------------------------------------------------------------------------
// K4: out = agg @ out_w + out_b ; result = dot * out[:, :64] + out[:, 64:]
// 128 threads, 4 nodes/iter. grid 625 x 20 x 4 = 50000.
// ---------------------------------------------------------------------------
__global__ void __launch_bounds__(128) out_kernel(
    const float* __restrict__ out_w,
    const float* __restrict__ out_b,
    float* __restrict__ out)
{
    __shared__ __align__(16) float s_a[4][64];
    __shared__ __align__(16) float s_o[4][128];
    const int t = threadIdx.x;

    ull wc[32];
#pragma unroll
    for (int k = 0; k < 32; k++)
        wc[k] = pack2(out_w[(2 * k) * 128 + t], out_w[(2 * k + 1) * 128 + t]);
    const float bc = out_b[t];

    const float* agg = (const float*)g_agg;
    for (int it = 0; it < VEC_IT; it++) {
        const int n0 = (blockIdx.x + it * VEC_GRID) * 4;

        for (int i = t; i < 256; i += 128)
            ((float*)s_a)[i] = agg[n0 * 64 + i];
        __syncthreads();

        ull acc[4];
#pragma unroll
        for (int nd = 0; nd < 4; nd++) acc[nd] = 0;
        const ull* a2 = (const ull*)s_a;
#pragma unroll
        for (int k = 0; k < 32; k++) {
            const ull w = wc[k];
#pragma unroll
            for (int nd = 0; nd < 4; nd++)
                ffma2(acc[nd], a2[nd * 32 + k], w);
        }
#pragma unroll
        for (int nd = 0; nd < 4; nd++)
            s_o[nd][t] = sum2(acc[nd]) + bc;
        __syncthreads();

        if (t < 64) {
#pragma unroll
            for (int nd = 0; nd < 4; nd++)
                out[(n0 + nd) * 64 + t] =
                    g_dot[(n0 + nd) * 64 + t] * s_o[nd][t] + s_o[nd][64 + t];
        }
        __syncthreads();
    }
}

// ---------------------------------------------------------------------------
extern "C" void kernel_launch(void* const* d_in, const int* in_sizes, int n_in,
                              void* d_out, int out_size)
{
    const float* node_feat = (const float*)d_in[0];
    const float* edge_feat = (const float*)d_in[1];
    const float* node_vec  = (const float*)d_in[2];
    const float* radial    = (const float*)d_in[3];
    const float* ln_g      = (const float*)d_in[4];
    const float* ln_b      = (const float*)d_in[5];
    const float* qkv_w     = (const float*)d_in[6];
    const float* qkv_b     = (const float*)d_in[7];
    const float* vec_w     = (const float*)d_in[8];
    const float* out_w     = (const float*)d_in[9];
    const float* out_b     = (const float*)d_in[10];
    const int*   row       = (const int*)d_in[11];
    const int*   col       = (const int*)d_in[12];
    float*       out       = (float*)d_out;

    zero_kernel<<<(NN * HHH + 255) / 256, 256>>>();
    qkv_kernel<<<QKV_GRID, 192>>>(node_feat, ln_g, ln_b, qkv_w, qkv_b);
    vec_kernel<<<VEC_GRID, 128>>>(node_vec, vec_w);
    edge_kernel<<<(EE * HHH + 255) / 256, 256>>>(
        (const float4*)edge_feat, radial, row, col);
    out_kernel<<<VEC_GRID, 128>>>(out_w, out_b, out);
}

// round 6
// speedup vs baseline: 1.3335x; 1.0539x over previous
#include <cuda_runtime.h>
#include <math.h>

#define NN  50000
#define EE  1250000
#define DIMM 64
#define HHH 16

typedef unsigned long long ull;

// Scratch (device globals). float4 layout: [node][head] = 16B
__device__ float4 g_q[NN * HHH];
__device__ float4 g_k[NN * HHH];
__device__ float4 g_v[NN * HHH];
__device__ float  g_dot[NN * DIMM];
__device__ float4 g_agg[NN * HHH];

// ---------------- packed f32x2 helpers (SASS FFMA2 / FADD2) -----------------
__device__ __forceinline__ void ffma2(ull &acc, ull a, ull b) {
    asm("fma.rn.f32x2 %0, %1, %2, %0;" : "+l"(acc) : "l"(a), "l"(b));
}
__device__ __forceinline__ ull pack2(float a, float b) {
    ull r; asm("mov.b64 %0, {%1,%2};" : "=l"(r) : "f"(a), "f"(b)); return r;
}
__device__ __forceinline__ float sum2(ull v) {
    float a, b; asm("mov.b64 {%0,%1}, %2;" : "=f"(a), "=f"(b) : "l"(v));
    return a + b;
}

// ---------------------------------------------------------------------------
// K1: LayerNorm + QKV. 192 threads (one per output col), 8 nodes per iter.
// grid 1250 x 5 iters x 8 nodes = 50000 exactly.
// Weights staged gmem->smem (coalesced), then packed into registers.
// ---------------------------------------------------------------------------
#define QKV_GRID 1250
#define QKV_IT   5

__global__ void __launch_bounds__(192) qkv_kernel(
    const float* __restrict__ node_feat,
    const float* __restrict__ ln_g,  const float* __restrict__ ln_b,
    const float* __restrict__ qkv_w, const float* __restrict__ qkv_b)
{
    __shared__ __align__(16) float s_w[64 * 192];   // 48 KB
    __shared__ __align__(16) float s_x [8][64];
    __shared__ __align__(16) float s_xn[8][64];
    __shared__ float s_g[64], s_b[64];
    __shared__ float s_mu[8], s_rs[8];
    const int t = threadIdx.x;  // 0..191

    // coalesced weight staging
    for (int i = t; i < 64 * 192; i += 192) s_w[i] = qkv_w[i];
    if (t < 64) { s_g[t] = ln_g[t]; s_b[t] = ln_b[t]; }
    __syncthreads();

    ull wc[32];
#pragma unroll
    for (int k = 0; k < 32; k++)
        wc[k] = pack2(s_w[(2 * k) * 192 + t], s_w[(2 * k + 1) * 192 + t]);
    const float bc = qkv_b[t];

    const int h = t / 12;
    const int r = t % 12;
    float* wbase;
    int    wd;
    if (r < 4)      { wbase = (float*)g_q; wd = r; }
    else if (r < 8) { wbase = (float*)g_k; wd = r - 4; }
    else            { wbase = (float*)g_v; wd = r - 8; }
    __syncthreads();

    for (int it = 0; it < QKV_IT; it++) {
        const int n0 = (blockIdx.x + it * QKV_GRID) * 8;

        for (int i = t; i < 512; i += 192)
            ((float*)s_x)[i] = node_feat[n0 * 64 + i];
        __syncthreads();

        // LN stats: 16 lanes per node (threads 0..127)
        if (t < 128) {
            const int nd = t >> 4, l = t & 15;
            const float4 v = *(const float4*)&s_x[nd][l * 4];
            float s  = v.x + v.y + v.z + v.w;
            float s2 = v.x * v.x + v.y * v.y + v.z * v.z + v.w * v.w;
#pragma unroll
            for (int o = 8; o >= 1; o >>= 1) {
                s  += __shfl_xor_sync(0xffffffffu, s,  o);
                s2 += __shfl_xor_sync(0xffffffffu, s2, o);
            }
            if (l == 0) {
                const float mu  = s * (1.f / 64.f);
                const float var = s2 * (1.f / 64.f) - mu * mu;
                s_mu[nd] = mu;
                s_rs[nd] = rsqrtf(var + 1e-5f);
            }
        }
        __syncthreads();

        for (int i = t; i < 512; i += 192) {
            const int nd = i >> 6, k = i & 63;
            ((float*)s_xn)[i] = (((float*)s_x)[i] - s_mu[nd]) * s_rs[nd] * s_g[k] + s_b[k];
        }
        __syncthreads();

        // GEMM: 8 independent accumulator chains per thread
        ull acc[8];
#pragma unroll
        for (int nd = 0; nd < 8; nd++) acc[nd] = 0;
        const ull* xn2 = (const ull*)s_xn;
#pragma unroll
        for (int k = 0; k < 32; k++) {
            const ull w = wc[k];
#pragma unroll
            for (int nd = 0; nd < 8; nd++)
                ffma2(acc[nd], xn2[nd * 32 + k], w);
        }
#pragma unroll
        for (int nd = 0; nd < 8; nd++)
            wbase[((n0 + nd) * 16 + h) * 4 + wd] = sum2(acc[nd]) + bc;
        __syncthreads();
    }
}

// ---------------------------------------------------------------------------
// K2: iv = node_vec @ vec_w ; input_dot. 128 threads, 4 nodes/iter.
// grid 1250 x 10 x 4 = 50000 exactly.
// ---------------------------------------------------------------------------
#define VEC_GRID 1250
#define VEC_IT   10

__global__ void __launch_bounds__(128) vec_kernel(
    const float* __restrict__ node_vec,
    const float* __restrict__ vec_w)
{
    __shared__ __align__(16) float s_w[64 * 128];   // 32 KB
    __shared__ __align__(16) float s_nv[4][192];
    __shared__ __align__(16) float s_iv[4][3][128];
    const int t = threadIdx.x;  // 0..127

    for (int i = t; i < 64 * 128; i += 128) s_w[i] = vec_w[i];
    __syncthreads();

    ull wc[32];
#pragma unroll
    for (int k = 0; k < 32; k++)
        wc[k] = pack2(s_w[(2 * k) * 128 + t], s_w[(2 * k + 1) * 128 + t]);
    __syncthreads();

    for (int it = 0; it < VEC_IT; it++) {
        const int n0 = (blockIdx.x + it * VEC_GRID) * 4;

        for (int i = t; i < 768; i += 128)
            ((float*)s_nv)[i] = node_vec[n0 * 192 + i];
        __syncthreads();

        // 12 independent chains (4 nodes x 3 vector components)
        ull acc[12];
#pragma unroll
        for (int c = 0; c < 12; c++) acc[c] = 0;
        const ull* nv2 = (const ull*)s_nv;
#pragma unroll
        for (int k = 0; k < 32; k++) {
            const ull w = wc[k];
#pragma unroll
            for (int c = 0; c < 12; c++)
                ffma2(acc[c], nv2[c * 32 + k], w);
        }
#pragma unroll
        for (int nd = 0; nd < 4; nd++)
#pragma unroll
            for (int a = 0; a < 3; a++)
                s_iv[nd][a][t] = sum2(acc[nd * 3 + a]);
        __syncthreads();

        if (t < 64) {
#pragma unroll
            for (int nd = 0; nd < 4; nd++) {
                float d = 0.f;
#pragma unroll
                for (int a = 0; a < 3; a++)
                    d += s_iv[nd][a][t] * s_iv[nd][a][64 + t];
                g_dot[(n0 + nd) * 64 + t] = d;
            }
        }
        __syncthreads();
    }
}

// ---------------------------------------------------------------------------
// Kz: zero the aggregation buffer
// ---------------------------------------------------------------------------
__global__ void zero_kernel()
{
    const int i = blockIdx.x * blockDim.x + threadIdx.x;
    if (i < NN * HHH) g_agg[i] = make_float4(0.f, 0.f, 0.f, 0.f);
}

// ---------------------------------------------------------------------------
// K3: edge phase. One thread per (edge, head). Vector atomics (red.v4.f32).
// Streams (__ldcs) bypass-evict; gather tables (__ldg) stay cached.
// ---------------------------------------------------------------------------
__global__ void __launch_bounds__(256) edge_kernel(
    const float4* __restrict__ edge_feat,
    const float*  __restrict__ radial,
    const int*    __restrict__ row,
    const int*    __restrict__ col)
{
    const int gid = blockIdx.x * blockDim.x + threadIdx.x;
    if (gid >= EE * HHH) return;
    const int e = gid >> 4;
    const int h = gid & 15;

    const int r = __ldcs(&row[e]);
    const int c = __ldcs(&col[e]);

    const float4 qv = __ldg(&g_q[r * 16 + h]);
    const float4 kv = __ldg(&g_k[c * 16 + h]);
    const float dot = qv.x * kv.x + qv.y * kv.y + qv.z * kv.z + qv.w * kv.w;

    // exact GELU: 0.5*x*(1+erf(x/sqrt(2)))
    const float attn = 0.5f * dot * (1.f + erff(dot * 0.70710678118654752f))
                     * __ldcs(&radial[e]);

    const float4 vv = __ldg(&g_v[c * 16 + h]);
    const float4 ef = __ldcs(&edge_feat[e * 16 + h]);

    float4* agg = &g_agg[r * 16 + h];
    asm volatile("red.global.add.v4.f32 [%0], {%1, %2, %3, %4};"
                 :: "l"(agg),
                    "f"(vv.x * ef.x * attn), "f"(vv.y * ef.y * attn),
                    "f"(vv.z * ef.z * attn), "f"(vv.w * ef.w * attn)
                 : "memory");
}

// ---------------------------------------------------------------------------
// K4: out = agg @ out_w + out_b ; result = dot * out[:, :64] + out[:, 64:]
// 128 threads, 4 nodes/iter. grid 1250 x 10 x 4 = 50000.
// ---------------------------------------------------------------------------
__global__ void __launch_bounds__(128) out_kernel(
    const float* __restrict__ out_w,
    const float* __restrict__ out_b,
    float* __restrict__ out)
{
    __shared__ __align__(16) float s_w[64 * 128];   // 32 KB
    __shared__ __align__(16) float s_a[4][64];
    __shared__ __align__(16) float s_o[4][128];
    const int t = threadIdx.x;

    for (int i = t; i < 64 * 128; i += 128) s_w[i] = out_w[i];
    __syncthreads();

    ull wc[32];
#pragma unroll
    for (int k = 0; k < 32; k++)
        wc[k] = pack2(s_w[(2 * k) * 128 + t], s_w[(2 * k + 1) * 128 + t]);
    const float bc = out_b[t];
    __syncthreads();

    const float* agg = (const float*)g_agg;
    for (int it = 0; it < VEC_IT; it++) {
        const int n0 = (blockIdx.x + it * VEC_GRID) * 4;

        for (int i = t; i < 256; i += 128)
            ((float*)s_a)[i] = agg[n0 * 64 + i];
        __syncthreads();

        ull acc[4];
#pragma unroll
        for (int nd = 0; nd < 4; nd++) acc[nd] = 0;
        const ull* a2 = (const ull*)s_a;
#pragma unroll
        for (int k = 0; k < 32; k++) {
            const ull w = wc[k];
#pragma unroll
            for (int nd = 0; nd < 4; nd++)
                ffma2(acc[nd], a2[nd * 32 + k], w);
        }
#pragma unroll
        for (int nd = 0; nd < 4; nd++)
            s_o[nd][t] = sum2(acc[nd]) + bc;
        __syncthreads();

        if (t < 64) {
#pragma unroll
            for (int nd = 0; nd < 4; nd++)
                out[(n0 + nd) * 64 + t] =
                    g_dot[(n0 + nd) * 64 + t] * s_o[nd][t] + s_o[nd][64 + t];
        }
        __syncthreads();
    }
}

// ---------------------------------------------------------------------------
extern "C" void kernel_launch(void* const* d_in, const int* in_sizes, int n_in,
                              void* d_out, int out_size)
{
    const float* node_feat = (const float*)d_in[0];
    const float* edge_feat = (const float*)d_in[1];
    const float* node_vec  = (const float*)d_in[2];
    const float* radial    = (const float*)d_in[3];
    const float* ln_g      = (const float*)d_in[4];
    const float* ln_b      = (const float*)d_in[5];
    const float* qkv_w     = (const float*)d_in[6];
    const float* qkv_b     = (const float*)d_in[7];
    const float* vec_w     = (const float*)d_in[8];
    const float* out_w     = (const float*)d_in[9];
    const float* out_b     = (const float*)d_in[10];
    const int*   row       = (const int*)d_in[11];
    const int*   col       = (const int*)d_in[12];
    float*       out       = (float*)d_out;

    zero_kernel<<<(NN * HHH + 255) / 256, 256>>>();
    qkv_kernel<<<QKV_GRID, 192>>>(node_feat, ln_g, ln_b, qkv_w, qkv_b);
    vec_kernel<<<VEC_GRID, 128>>>(node_vec, vec_w);
    edge_kernel<<<(EE * HHH + 255) / 256, 256>>>(
        (const float4*)edge_feat, radial, row, col);
    out_kernel<<<VEC_GRID, 128>>>(out_w, out_b, out);
}

// round 7
// speedup vs baseline: 1.4235x; 1.0674x over previous
#include <cuda_runtime.h>
#include <math.h>

#define NN  50000
#define EE  1250000
#define DIMM 64
#define HHH 16

typedef unsigned long long ull;

// Scratch (device globals).
__device__ float4 g_q [NN * HHH];        // [node][head] 16B
__device__ float4 g_kv[NN * HHH * 2];    // [node][head][{k,v}] 32B per (node,head)
__device__ float  g_dot[NN * DIMM];
__device__ float4 g_agg[NN * HHH];

// ---------------- packed f32x2 helpers (SASS FFMA2) -------------------------
__device__ __forceinline__ void ffma2(ull &acc, ull a, ull b) {
    asm("fma.rn.f32x2 %0, %1, %2, %0;" : "+l"(acc) : "l"(a), "l"(b));
}
__device__ __forceinline__ ull pack2(float a, float b) {
    ull r; asm("mov.b64 %0, {%1,%2};" : "=l"(r) : "f"(a), "f"(b)); return r;
}
__device__ __forceinline__ float sum2(ull v) {
    float a, b; asm("mov.b64 {%0,%1}, %2;" : "=f"(a), "=f"(b) : "l"(v));
    return a + b;
}

// ---------------------------------------------------------------------------
// K1: LayerNorm + QKV. 192 threads (one per output col), 8 nodes/iter.
// grid 1250 x 5 x 8 = 50000. Activations via LDS.128 (longlong2).
// ---------------------------------------------------------------------------
#define QKV_GRID 1250
#define QKV_IT   5

__global__ void __launch_bounds__(192) qkv_kernel(
    const float* __restrict__ node_feat,
    const float* __restrict__ ln_g,  const float* __restrict__ ln_b,
    const float* __restrict__ qkv_w, const float* __restrict__ qkv_b)
{
    __shared__ __align__(16) float s_w[64 * 192];   // 48 KB
    __shared__ __align__(16) float s_x [8][64];
    __shared__ __align__(16) float s_xn[8][64];
    __shared__ float s_g[64], s_b[64];
    __shared__ float s_mu[8], s_rs[8];
    const int t = threadIdx.x;  // 0..191

    for (int i = t; i < 64 * 192; i += 192) s_w[i] = qkv_w[i];
    if (t < 64) { s_g[t] = ln_g[t]; s_b[t] = ln_b[t]; }
    __syncthreads();

    ull wc[32];
#pragma unroll
    for (int k = 0; k < 32; k++)
        wc[k] = pack2(s_w[(2 * k) * 192 + t], s_w[(2 * k + 1) * 192 + t]);
    const float bc = qkv_b[t];

    const int h = t / 12;
    const int r = t % 12;
    float* wbase;
    int    wmul, wd;
    if (r < 4) { wbase = (float*)g_q;  wmul = 4; wd = r; }
    else       { wbase = (float*)g_kv; wmul = 8; wd = r - 4; }  // k:0-3, v:4-7
    __syncthreads();

    for (int it = 0; it < QKV_IT; it++) {
        const int n0 = (blockIdx.x + it * QKV_GRID) * 8;

        for (int i = t; i < 512; i += 192)
            ((float*)s_x)[i] = node_feat[n0 * 64 + i];
        __syncthreads();

        if (t < 128) {
            const int nd = t >> 4, l = t & 15;
            const float4 v = *(const float4*)&s_x[nd][l * 4];
            float s  = v.x + v.y + v.z + v.w;
            float s2 = v.x * v.x + v.y * v.y + v.z * v.z + v.w * v.w;
#pragma unroll
            for (int o = 8; o >= 1; o >>= 1) {
                s  += __shfl_xor_sync(0xffffffffu, s,  o);
                s2 += __shfl_xor_sync(0xffffffffu, s2, o);
            }
            if (l == 0) {
                const float mu  = s * (1.f / 64.f);
                const float var = s2 * (1.f / 64.f) - mu * mu;
                s_mu[nd] = mu;
                s_rs[nd] = rsqrtf(var + 1e-5f);
            }
        }
        __syncthreads();

        for (int i = t; i < 512; i += 192) {
            const int nd = i >> 6, k = i & 63;
            ((float*)s_xn)[i] = (((float*)s_x)[i] - s_mu[nd]) * s_rs[nd] * s_g[k] + s_b[k];
        }
        __syncthreads();

        // GEMM: 8 chains, LDS.128 feeds 2 FFMA2
        ull acc[8];
#pragma unroll
        for (int nd = 0; nd < 8; nd++) acc[nd] = 0;
        const longlong2* xn4 = (const longlong2*)s_xn;   // 16 per node
#pragma unroll
        for (int k = 0; k < 16; k++) {
            const ull w0 = wc[2 * k], w1 = wc[2 * k + 1];
#pragma unroll
            for (int nd = 0; nd < 8; nd++) {
                const longlong2 v = xn4[nd * 16 + k];
                ffma2(acc[nd], (ull)v.x, w0);
                ffma2(acc[nd], (ull)v.y, w1);
            }
        }
#pragma unroll
        for (int nd = 0; nd < 8; nd++)
            wbase[((n0 + nd) * 16 + h) * wmul + wd] = sum2(acc[nd]) + bc;
        __syncthreads();
    }
}

// ---------------------------------------------------------------------------
// K2: iv = node_vec @ vec_w ; input_dot. 128 threads, 4 nodes/iter.
// grid 1250 x 10 x 4 = 50000.
// ---------------------------------------------------------------------------
#define VEC_GRID 1250
#define VEC_IT   10

__global__ void __launch_bounds__(128) vec_kernel(
    const float* __restrict__ node_vec,
    const float* __restrict__ vec_w)
{
    __shared__ __align__(16) float s_w[64 * 128];   // 32 KB
    __shared__ __align__(16) float s_nv[4][192];
    __shared__ __align__(16) float s_iv[4][3][128];
    const int t = threadIdx.x;

    for (int i = t; i < 64 * 128; i += 128) s_w[i] = vec_w[i];
    __syncthreads();

    ull wc[32];
#pragma unroll
    for (int k = 0; k < 32; k++)
        wc[k] = pack2(s_w[(2 * k) * 128 + t], s_w[(2 * k + 1) * 128 + t]);
    __syncthreads();

    for (int it = 0; it < VEC_IT; it++) {
        const int n0 = (blockIdx.x + it * VEC_GRID) * 4;

        for (int i = t; i < 768; i += 128)
            ((float*)s_nv)[i] = node_vec[n0 * 192 + i];
        __syncthreads();

        // 12 chains (4 nodes x 3 components), LDS.128 feeds 2 FFMA2
        ull acc[12];
#pragma unroll
        for (int c = 0; c < 12; c++) acc[c] = 0;
        const longlong2* nv4 = (const longlong2*)s_nv;  // 16 per chain
#pragma unroll
        for (int k = 0; k < 16; k++) {
            const ull w0 = wc[2 * k], w1 = wc[2 * k + 1];
#pragma unroll
            for (int c = 0; c < 12; c++) {
                const longlong2 v = nv4[c * 16 + k];
                ffma2(acc[c], (ull)v.x, w0);
                ffma2(acc[c], (ull)v.y, w1);
            }
        }
#pragma unroll
        for (int nd = 0; nd < 4; nd++)
#pragma unroll
            for (int a = 0; a < 3; a++)
                s_iv[nd][a][t] = sum2(acc[nd * 3 + a]);
        __syncthreads();

        if (t < 64) {
#pragma unroll
            for (int nd = 0; nd < 4; nd++) {
                float d = 0.f;
#pragma unroll
                for (int a = 0; a < 3; a++)
                    d += s_iv[nd][a][t] * s_iv[nd][a][64 + t];
                g_dot[(n0 + nd) * 64 + t] = d;
            }
        }
        __syncthreads();
    }
}

// ---------------------------------------------------------------------------
// Kz: zero the aggregation buffer
// ---------------------------------------------------------------------------
__global__ void zero_kernel()
{
    const int i = blockIdx.x * blockDim.x + threadIdx.x;
    if (i < NN * HHH) g_agg[i] = make_float4(0.f, 0.f, 0.f, 0.f);
}

// ---------------------------------------------------------------------------
// K3: edge phase. One thread per (edge, head). k|v fused gather (32B sector),
// vector atomics.
// ---------------------------------------------------------------------------
__global__ void __launch_bounds__(256) edge_kernel(
    const float4* __restrict__ edge_feat,
    const float*  __restrict__ radial,
    const int*    __restrict__ row,
    const int*    __restrict__ col)
{
    const int gid = blockIdx.x * blockDim.x + threadIdx.x;
    if (gid >= EE * HHH) return;
    const int e = gid >> 4;
    const int h = gid & 15;

    const int r = __ldcs(&row[e]);
    const int c = __ldcs(&col[e]);

    const float4 qv = __ldg(&g_q[r * 16 + h]);
    const float4 kv = __ldg(&g_kv[(c * 16 + h) * 2]);      // same 32B sector
    const float4 vv = __ldg(&g_kv[(c * 16 + h) * 2 + 1]);  // as this one

    const float dot = qv.x * kv.x + qv.y * kv.y + qv.z * kv.z + qv.w * kv.w;

    // exact GELU: 0.5*x*(1+erf(x/sqrt(2)))
    const float attn = 0.5f * dot * (1.f + erff(dot * 0.70710678118654752f))
                     * __ldcs(&radial[e]);

    const float4 ef = __ldcs(&edge_feat[e * 16 + h]);

    float4* agg = &g_agg[r * 16 + h];
    asm volatile("red.global.add.v4.f32 [%0], {%1, %2, %3, %4};"
                 :: "l"(agg),
                    "f"(vv.x * ef.x * attn), "f"(vv.y * ef.y * attn),
                    "f"(vv.z * ef.z * attn), "f"(vv.w * ef.w * attn)
                 : "memory");
}

// ---------------------------------------------------------------------------
// K4: out = agg @ out_w + out_b ; result = dot * out[:, :64] + out[:, 64:]
// ---------------------------------------------------------------------------
__global__ void __launch_bounds__(128) out_kernel(
    const float* __restrict__ out_w,
    const float* __restrict__ out_b,
    float* __restrict__ out)
{
    __shared__ __align__(16) float s_w[64 * 128];   // 32 KB
    __shared__ __align__(16) float s_a[4][64];
    __shared__ __align__(16) float s_o[4][128];
    const int t = threadIdx.x;

    for (int i = t; i < 64 * 128; i += 128) s_w[i] = out_w[i];
    __syncthreads();

    ull wc[32];
#pragma unroll
    for (int k = 0; k < 32; k++)
        wc[k] = pack2(s_w[(2 * k) * 128 + t], s_w[(2 * k + 1) * 128 + t]);
    const float bc = out_b[t];
    __syncthreads();

    const float* agg = (const float*)g_agg;
    for (int it = 0; it < VEC_IT; it++) {
        const int n0 = (blockIdx.x + it * VEC_GRID) * 4;

        for (int i = t; i < 256; i += 128)
            ((float*)s_a)[i] = agg[n0 * 64 + i];
        __syncthreads();

        ull acc[4];
#pragma unroll
        for (int nd = 0; nd < 4; nd++) acc[nd] = 0;
        const longlong2* a4 = (const longlong2*)s_a;   // 16 per node
#pragma unroll
        for (int k = 0; k < 16; k++) {
            const ull w0 = wc[2 * k], w1 = wc[2 * k + 1];
#pragma unroll
            for (int nd = 0; nd < 4; nd++) {
                const longlong2 v = a4[nd * 16 + k];
                ffma2(acc[nd], (ull)v.x, w0);
                ffma2(acc[nd], (ull)v.y, w1);
            }
        }
#pragma unroll
        for (int nd = 0; nd < 4; nd++)
            s_o[nd][t] = sum2(acc[nd]) + bc;
        __syncthreads();

        if (t < 64) {
#pragma unroll
            for (int nd = 0; nd < 4; nd++)
                out[(n0 + nd) * 64 + t] =
                    g_dot[(n0 + nd) * 64 + t] * s_o[nd][t] + s_o[nd][64 + t];
        }
        __syncthreads();
    }
}

// ---------------------------------------------------------------------------
// Launch order: zero, qkv, edge, vec, out
//   edge needs zero + qkv;  out needs edge + vec;  vec independent.
// ---------------------------------------------------------------------------
extern "C" void kernel_launch(void* const* d_in, const int* in_sizes, int n_in,
                              void* d_out, int out_size)
{
    const float* node_feat = (const float*)d_in[0];
    const float* edge_feat = (const float*)d_in[1];
    const float* node_vec  = (const float*)d_in[2];
    const float* radial    = (const float*)d_in[3];
    const float* ln_g      = (const float*)d_in[4];
    const float* ln_b      = (const float*)d_in[5];
    const float* qkv_w     = (const float*)d_in[6];
    const float* qkv_b     = (const float*)d_in[7];
    const float* vec_w     = (const float*)d_in[8];
    const float* out_w     = (const float*)d_in[9];
    const float* out_b     = (const float*)d_in[10];
    const int*   row       = (const int*)d_in[11];
    const int*   col       = (const int*)d_in[12];
    float*       out       = (float*)d_out;

    zero_kernel<<<(NN * HHH + 255) / 256, 256>>>();
    qkv_kernel<<<QKV_GRID, 192>>>(node_feat, ln_g, ln_b, qkv_w, qkv_b);
    edge_kernel<<<(EE * HHH + 255) / 256, 256>>>(
        (const float4*)edge_feat, radial, row, col);
    vec_kernel<<<VEC_GRID, 128>>>(node_vec, vec_w);
    out_kernel<<<VEC_GRID, 128>>>(out_w, out_b, out);
}

// round 9
// speedup vs baseline: 1.5319x; 1.0761x over previous
#include <cuda_runtime.h>
#include <math.h>

#define NN  50000
#define EE  1250000
#define DIMM 64
#define HHH 16

typedef unsigned long long ull;

// Scratch (device globals).
__device__ float4 g_q [NN * HHH];        // [node][head] 16B
__device__ float4 g_kv[NN * HHH * 2];    // [node][head][{k,v}] 32B per (node,head)
__device__ float  g_dot[NN * DIMM];
__device__ float4 g_agg[NN * HHH];

// ---------------- packed f32x2 helpers (SASS FFMA2) -------------------------
__device__ __forceinline__ void ffma2(ull &acc, ull a, ull b) {
    asm("fma.rn.f32x2 %0, %1, %2, %0;" : "+l"(acc) : "l"(a), "l"(b));
}
__device__ __forceinline__ ull pack2(float a, float b) {
    ull r; asm("mov.b64 %0, {%1,%2};" : "=l"(r) : "f"(a), "f"(b)); return r;
}
__device__ __forceinline__ float sum2(ull v) {
    float a, b; asm("mov.b64 {%0,%1}, %2;" : "=f"(a), "=f"(b) : "l"(v));
    return a + b;
}

// ---------------------------------------------------------------------------
// K1: LayerNorm + QKV. 192 threads (one per output col), 8 nodes/iter.
// grid 1250 x 5 x 8 = 50000. Weights packed in SMEM (ulonglong2), acts LDS.128.
// ---------------------------------------------------------------------------
#define QKV_GRID 1250
#define QKV_IT   5

__global__ void __launch_bounds__(192, 4) qkv_kernel(
    const float* __restrict__ node_feat,
    const float* __restrict__ ln_g,  const float* __restrict__ ln_b,
    const float* __restrict__ qkv_w, const float* __restrict__ qkv_b)
{
    __shared__ __align__(16) ulonglong2 spw[16 * 192];   // 48 KB packed weights
    __shared__ __align__(16) float s_x [8][64];
    __shared__ __align__(16) float s_xn[8][64];
    __shared__ float s_g[64], s_b[64];
    __shared__ float s_mu[8], s_rs[8];
    const int t = threadIdx.x;  // 0..191

    // pack weights: spw[kp*192+t] = {pack2(w[4kp][t],w[4kp+1][t]), pack2(w[4kp+2][t],w[4kp+3][t])}
#pragma unroll
    for (int kp = 0; kp < 16; kp++) {
        ulonglong2 p;
        p.x = pack2(qkv_w[(4 * kp    ) * 192 + t], qkv_w[(4 * kp + 1) * 192 + t]);
        p.y = pack2(qkv_w[(4 * kp + 2) * 192 + t], qkv_w[(4 * kp + 3) * 192 + t]);
        spw[kp * 192 + t] = p;
    }
    const float bc = qkv_b[t];
    if (t < 64) { s_g[t] = ln_g[t]; s_b[t] = ln_b[t]; }

    const int h = t / 12;
    const int r = t % 12;
    float* wbase;
    int    wmul, wd;
    if (r < 4) { wbase = (float*)g_q;  wmul = 4; wd = r; }
    else       { wbase = (float*)g_kv; wmul = 8; wd = r - 4; }  // k:0-3, v:4-7
    __syncthreads();

    for (int it = 0; it < QKV_IT; it++) {
        const int n0 = (blockIdx.x + it * QKV_GRID) * 8;

        for (int i = t; i < 512; i += 192)
            ((float*)s_x)[i] = node_feat[n0 * 64 + i];
        __syncthreads();

        if (t < 128) {
            const int nd = t >> 4, l = t & 15;
            const float4 v = *(const float4*)&s_x[nd][l * 4];
            float s  = v.x + v.y + v.z + v.w;
            float s2 = v.x * v.x + v.y * v.y + v.z * v.z + v.w * v.w;
#pragma unroll
            for (int o = 8; o >= 1; o >>= 1) {
                s  += __shfl_xor_sync(0xffffffffu, s,  o);
                s2 += __shfl_xor_sync(0xffffffffu, s2, o);
            }
            if (l == 0) {
                const float mu  = s * (1.f / 64.f);
                const float var = s2 * (1.f / 64.f) - mu * mu;
                s_mu[nd] = mu;
                s_rs[nd] = rsqrtf(var + 1e-5f);
            }
        }
        __syncthreads();

        for (int i = t; i < 512; i += 192) {
            const int nd = i >> 6, k = i & 63;
            ((float*)s_xn)[i] = (((float*)s_x)[i] - s_mu[nd]) * s_rs[nd] * s_g[k] + s_b[k];
        }
        __syncthreads();

        ull acc[8];
#pragma unroll
        for (int nd = 0; nd < 8; nd++) acc[nd] = 0;
        const ulonglong2* xn4 = (const ulonglong2*)s_xn;   // 16 per node
#pragma unroll
        for (int kp = 0; kp < 16; kp++) {
            const ulonglong2 w = spw[kp * 192 + t];
#pragma unroll
            for (int nd = 0; nd < 8; nd++) {
                const ulonglong2 v = xn4[nd * 16 + kp];
                ffma2(acc[nd], v.x, w.x);
                ffma2(acc[nd], v.y, w.y);
            }
        }
#pragma unroll
        for (int nd = 0; nd < 8; nd++)
            wbase[((n0 + nd) * 16 + h) * wmul + wd] = sum2(acc[nd]) + bc;
        __syncthreads();
    }
}

// ---------------------------------------------------------------------------
// K2: iv = node_vec @ vec_w ; input_dot. 128 threads, 4 nodes/iter.
// grid 1250 x 10 x 4 = 50000.
// ---------------------------------------------------------------------------
#define VEC_GRID 1250
#define VEC_IT   10

__global__ void __launch_bounds__(128, 6) vec_kernel(
    const float* __restrict__ node_vec,
    const float* __restrict__ vec_w)
{
    __shared__ __align__(16) ulonglong2 spw[16 * 128];   // 32 KB
    __shared__ __align__(16) float s_nv[4][192];
    __shared__ __align__(16) float s_iv[4][3][128];
    const int t = threadIdx.x;

#pragma unroll
    for (int kp = 0; kp < 16; kp++) {
        ulonglong2 p;
        p.x = pack2(vec_w[(4 * kp    ) * 128 + t], vec_w[(4 * kp + 1) * 128 + t]);
        p.y = pack2(vec_w[(4 * kp + 2) * 128 + t], vec_w[(4 * kp + 3) * 128 + t]);
        spw[kp * 128 + t] = p;
    }
    __syncthreads();

    for (int it = 0; it < VEC_IT; it++) {
        const int n0 = (blockIdx.x + it * VEC_GRID) * 4;

        for (int i = t; i < 768; i += 128)
            ((float*)s_nv)[i] = node_vec[n0 * 192 + i];
        __syncthreads();

        // 12 chains (4 nodes x 3 components)
        ull acc[12];
#pragma unroll
        for (int c = 0; c < 12; c++) acc[c] = 0;
        const ulonglong2* nv4 = (const ulonglong2*)s_nv;  // 16 per chain
#pragma unroll
        for (int kp = 0; kp < 16; kp++) {
            const ulonglong2 w = spw[kp * 128 + t];
#pragma unroll
            for (int c = 0; c < 12; c++) {
                const ulonglong2 v = nv4[c * 16 + kp];
                ffma2(acc[c], v.x, w.x);
                ffma2(acc[c], v.y, w.y);
            }
        }
#pragma unroll
        for (int nd = 0; nd < 4; nd++)
#pragma unroll
            for (int a = 0; a < 3; a++)
                s_iv[nd][a][t] = sum2(acc[nd * 3 + a]);
        __syncthreads();

        if (t < 64) {
#pragma unroll
            for (int nd = 0; nd < 4; nd++) {
                float d = 0.f;
#pragma unroll
                for (int a = 0; a < 3; a++)
                    d += s_iv[nd][a][t] * s_iv[nd][a][64 + t];
                g_dot[(n0 + nd) * 64 + t] = d;
            }
        }
        __syncthreads();
    }
}

// ---------------------------------------------------------------------------
// Kz: zero the aggregation buffer
// ---------------------------------------------------------------------------
__global__ void zero_kernel()
{
    const int i = blockIdx.x * blockDim.x + threadIdx.x;
    if (i < NN * HHH) g_agg[i] = make_float4(0.f, 0.f, 0.f, 0.f);
}

// ---------------------------------------------------------------------------
// K3: edge phase. One thread per (edge, head). k|v fused gather (32B sector),
// vector atomics.
// ---------------------------------------------------------------------------
__global__ void __launch_bounds__(256) edge_kernel(
    const float4* __restrict__ edge_feat,
    const float*  __restrict__ radial,
    const int*    __restrict__ row,
    const int*    __restrict__ col)
{
    const int gid = blockIdx.x * blockDim.x + threadIdx.x;
    if (gid >= EE * HHH) return;
    const int e = gid >> 4;
    const int h = gid & 15;

    const int r = __ldcs(&row[e]);
    const int c = __ldcs(&col[e]);

    const float4 qv = __ldg(&g_q[r * 16 + h]);
    const float4 kv = __ldg(&g_kv[(c * 16 + h) * 2]);
    const float4 vv = __ldg(&g_kv[(c * 16 + h) * 2 + 1]);

    const float dot = qv.x * kv.x + qv.y * kv.y + qv.z * kv.z + qv.w * kv.w;

    // exact GELU: 0.5*x*(1+erf(x/sqrt(2)))
    const float attn = 0.5f * dot * (1.f + erff(dot * 0.70710678118654752f))
                     * __ldcs(&radial[e]);

    const float4 ef = __ldcs(&edge_feat[e * 16 + h]);

    float4* agg = &g_agg[r * 16 + h];
    asm volatile("red.global.add.v4.f32 [%0], {%1, %2, %3, %4};"
                 :: "l"(agg),
                    "f"(vv.x * ef.x * attn), "f"(vv.y * ef.y * attn),
                    "f"(vv.z * ef.z * attn), "f"(vv.w * ef.w * attn)
                 : "memory");
}

// ---------------------------------------------------------------------------
// K4: out = agg @ out_w + out_b ; result = dot * out[:, :64] + out[:, 64:]
// ---------------------------------------------------------------------------
__global__ void __launch_bounds__(128, 6) out_kernel(
    const float* __restrict__ out_w,
    const float* __restrict__ out_b,
    float* __restrict__ out)
{
    __shared__ __align__(16) ulonglong2 spw[16 * 128];   // 32 KB
    __shared__ __align__(16) float s_a[4][64];
    __shared__ __align__(16) float s_o[4][128];
    const int t = threadIdx.x;

#pragma unroll
    for (int kp = 0; kp < 16; kp++) {
        ulonglong2 p;
        p.x = pack2(out_w[(4 * kp    ) * 128 + t], out_w[(4 * kp + 1) * 128 + t]);
        p.y = pack2(out_w[(4 * kp + 2) * 128 + t], out_w[(4 * kp + 3) * 128 + t]);
        spw[kp * 128 + t] = p;
    }
    const float bc = out_b[t];
    __syncthreads();

    const float* agg = (const float*)g_agg;
    for (int it = 0; it < VEC_IT; it++) {
        const int n0 = (blockIdx.x + it * VEC_GRID) * 4;

        for (int i = t; i < 256; i += 128)
            ((float*)s_a)[i] = agg[n0 * 64 + i];
        __syncthreads();

        ull acc[4];
#pragma unroll
        for (int nd = 0; nd < 4; nd++) acc[nd] = 0;
        const ulonglong2* a4 = (const ulonglong2*)s_a;   // 16 per node
#pragma unroll
        for (int kp = 0; kp < 16; kp++) {
            const ulonglong2 w = spw[kp * 128 + t];
#pragma unroll
            for (int nd = 0; nd < 4; nd++) {
                const ulonglong2 v = a4[nd * 16 + kp];
                ffma2(acc[nd], v.x, w.x);
                ffma2(acc[nd], v.y, w.y);
            }
        }
#pragma unroll
        for (int nd = 0; nd < 4; nd++)
            s_o[nd][t] = sum2(acc[nd]) + bc;
        __syncthreads();

        if (t < 64) {
#pragma unroll
            for (int nd = 0; nd < 4; nd++)
                out[(n0 + nd) * 64 + t] =
                    g_dot[(n0 + nd) * 64 + t] * s_o[nd][t] + s_o[nd][64 + t];
        }
        __syncthreads();
    }
}

// ---------------------------------------------------------------------------
// Launch order: zero, qkv, edge, vec, out
// ---------------------------------------------------------------------------
extern "C" void kernel_launch(void* const* d_in, const int* in_sizes, int n_in,
                              void* d_out, int out_size)
{
    const float* node_feat = (const float*)d_in[0];
    const float* edge_feat = (const float*)d_in[1];
    const float* node_vec  = (const float*)d_in[2];
    const float* radial    = (const float*)d_in[3];
    const float* ln_g      = (const float*)d_in[4];
    const float* ln_b      = (const float*)d_in[5];
    const float* qkv_w     = (const float*)d_in[6];
    const float* qkv_b     = (const float*)d_in[7];
    const float* vec_w     = (const float*)d_in[8];
    const float* out_w     = (const float*)d_in[9];
    const float* out_b     = (const float*)d_in[10];
    const int*   row       = (const int*)d_in[11];
    const int*   col       = (const int*)d_in[12];
    float*       out       = (float*)d_out;

    zero_kernel<<<(NN * HHH + 255) / 256, 256>>>();
    qkv_kernel<<<QKV_GRID, 192>>>(node_feat, ln_g, ln_b, qkv_w, qkv_b);
    edge_kernel<<<(EE * HHH + 255) / 256, 256>>>(
        (const float4*)edge_feat, radial, row, col);
    vec_kernel<<<VEC_GRID, 128>>>(node_vec, vec_w);
    out_kernel<<<VEC_GRID, 128>>>(out_w, out_b, out);
}

// round 10
// speedup vs baseline: 1.5985x; 1.0435x over previous
#include <cuda_runtime.h>
#include <math.h>

#define NN  50000
#define EE  1250000
#define DIMM 64
#define HHH 16

typedef unsigned long long ull;

// Scratch (device globals).
__device__ float4 g_q [NN * HHH];        // [node][head] 16B
__device__ float4 g_kv[NN * HHH * 2];    // [node][head][{k,v}] 32B per (node,head)
__device__ float  g_dot[NN * DIMM];
__device__ float4 g_agg[NN * HHH];

// ---------------- packed f32x2 helpers (SASS FFMA2) -------------------------
__device__ __forceinline__ void ffma2(ull &acc, ull a, ull b) {
    asm("fma.rn.f32x2 %0, %1, %2, %0;" : "+l"(acc) : "l"(a), "l"(b));
}
__device__ __forceinline__ ull pack2(float a, float b) {
    ull r; asm("mov.b64 %0, {%1,%2};" : "=l"(r) : "f"(a), "f"(b)); return r;
}
__device__ __forceinline__ float sum2(ull v) {
    float a, b; asm("mov.b64 {%0,%1}, %2;" : "=f"(a), "=f"(b) : "l"(v));
    return a + b;
}

// ---------------------------------------------------------------------------
// K1: LayerNorm + QKV. 192 threads (one per output col), 8 nodes/iter.
// grid 1250 x 5 x 8 = 50000. Weights packed in SMEM (ulonglong2), acts LDS.128.
// ---------------------------------------------------------------------------
#define QKV_GRID 1250
#define QKV_IT   5

__global__ void __launch_bounds__(192, 4) qkv_kernel(
    const float* __restrict__ node_feat,
    const float* __restrict__ ln_g,  const float* __restrict__ ln_b,
    const float* __restrict__ qkv_w, const float* __restrict__ qkv_b)
{
    __shared__ __align__(16) ulonglong2 spw[16 * 192];   // 48 KB packed weights
    __shared__ __align__(16) float s_x [8][64];
    __shared__ __align__(16) float s_xn[8][64];
    __shared__ float s_g[64], s_b[64];
    __shared__ float s_mu[8], s_rs[8];
    const int t = threadIdx.x;  // 0..191

#pragma unroll
    for (int kp = 0; kp < 16; kp++) {
        ulonglong2 p;
        p.x = pack2(qkv_w[(4 * kp    ) * 192 + t], qkv_w[(4 * kp + 1) * 192 + t]);
        p.y = pack2(qkv_w[(4 * kp + 2) * 192 + t], qkv_w[(4 * kp + 3) * 192 + t]);
        spw[kp * 192 + t] = p;
    }
    const float bc = qkv_b[t];
    if (t < 64) { s_g[t] = ln_g[t]; s_b[t] = ln_b[t]; }

    const int h = t / 12;
    const int r = t % 12;
    float* wbase;
    int    wmul, wd;
    if (r < 4) { wbase = (float*)g_q;  wmul = 4; wd = r; }
    else       { wbase = (float*)g_kv; wmul = 8; wd = r - 4; }  // k:0-3, v:4-7
    __syncthreads();

    for (int it = 0; it < QKV_IT; it++) {
        const int n0 = (blockIdx.x + it * QKV_GRID) * 8;

        for (int i = t; i < 512; i += 192)
            ((float*)s_x)[i] = node_feat[n0 * 64 + i];
        __syncthreads();

        if (t < 128) {
            const int nd = t >> 4, l = t & 15;
            const float4 v = *(const float4*)&s_x[nd][l * 4];
            float s  = v.x + v.y + v.z + v.w;
            float s2 = v.x * v.x + v.y * v.y + v.z * v.z + v.w * v.w;
#pragma unroll
            for (int o = 8; o >= 1; o >>= 1) {
                s  += __shfl_xor_sync(0xffffffffu, s,  o);
                s2 += __shfl_xor_sync(0xffffffffu, s2, o);
            }
            if (l == 0) {
                const float mu  = s * (1.f / 64.f);
                const float var = s2 * (1.f / 64.f) - mu * mu;
                s_mu[nd] = mu;
                s_rs[nd] = rsqrtf(var + 1e-5f);
            }
        }
        __syncthreads();

        for (int i = t; i < 512; i += 192) {
            const int nd = i >> 6, k = i & 63;
            ((float*)s_xn)[i] = (((float*)s_x)[i] - s_mu[nd]) * s_rs[nd] * s_g[k] + s_b[k];
        }
        __syncthreads();

        ull acc[8];
#pragma unroll
        for (int nd = 0; nd < 8; nd++) acc[nd] = 0;
        const ulonglong2* xn4 = (const ulonglong2*)s_xn;   // 16 per node
#pragma unroll
        for (int kp = 0; kp < 16; kp++) {
            const ulonglong2 w = spw[kp * 192 + t];
#pragma unroll
            for (int nd = 0; nd < 8; nd++) {
                const ulonglong2 v = xn4[nd * 16 + kp];
                ffma2(acc[nd], v.x, w.x);
                ffma2(acc[nd], v.y, w.y);
            }
        }
#pragma unroll
        for (int nd = 0; nd < 8; nd++)
            wbase[((n0 + nd) * 16 + h) * wmul + wd] = sum2(acc[nd]) + bc;
        __syncthreads();
    }
}

// ---------------------------------------------------------------------------
// K2: iv = node_vec @ vec_w ; input_dot. 128 threads, 4 nodes/iter.
// grid 1250 x 10 x 4 = 50000.  (runs on side stream, concurrent with edge)
// ---------------------------------------------------------------------------
#define VEC_GRID 1250
#define VEC_IT   10

__global__ void __launch_bounds__(128, 6) vec_kernel(
    const float* __restrict__ node_vec,
    const float* __restrict__ vec_w)
{
    __shared__ __align__(16) ulonglong2 spw[16 * 128];   // 32 KB
    __shared__ __align__(16) float s_nv[4][192];
    __shared__ __align__(16) float s_iv[4][3][128];
    const int t = threadIdx.x;

#pragma unroll
    for (int kp = 0; kp < 16; kp++) {
        ulonglong2 p;
        p.x = pack2(vec_w[(4 * kp    ) * 128 + t], vec_w[(4 * kp + 1) * 128 + t]);
        p.y = pack2(vec_w[(4 * kp + 2) * 128 + t], vec_w[(4 * kp + 3) * 128 + t]);
        spw[kp * 128 + t] = p;
    }
    __syncthreads();

    for (int it = 0; it < VEC_IT; it++) {
        const int n0 = (blockIdx.x + it * VEC_GRID) * 4;

        for (int i = t; i < 768; i += 128)
            ((float*)s_nv)[i] = node_vec[n0 * 192 + i];
        __syncthreads();

        ull acc[12];
#pragma unroll
        for (int c = 0; c < 12; c++) acc[c] = 0;
        const ulonglong2* nv4 = (const ulonglong2*)s_nv;  // 16 per chain
#pragma unroll
        for (int kp = 0; kp < 16; kp++) {
            const ulonglong2 w = spw[kp * 128 + t];
#pragma unroll
            for (int c = 0; c < 12; c++) {
                const ulonglong2 v = nv4[c * 16 + kp];
                ffma2(acc[c], v.x, w.x);
                ffma2(acc[c], v.y, w.y);
            }
        }
#pragma unroll
        for (int nd = 0; nd < 4; nd++)
#pragma unroll
            for (int a = 0; a < 3; a++)
                s_iv[nd][a][t] = sum2(acc[nd * 3 + a]);
        __syncthreads();

        if (t < 64) {
#pragma unroll
            for (int nd = 0; nd < 4; nd++) {
                float d = 0.f;
#pragma unroll
                for (int a = 0; a < 3; a++)
                    d += s_iv[nd][a][t] * s_iv[nd][a][64 + t];
                g_dot[(n0 + nd) * 64 + t] = d;
            }
        }
        __syncthreads();
    }
}

// ---------------------------------------------------------------------------
// Kz: zero the aggregation buffer
// ---------------------------------------------------------------------------
__global__ void zero_kernel()
{
    const int i = blockIdx.x * blockDim.x + threadIdx.x;
    if (i < NN * HHH) g_agg[i] = make_float4(0.f, 0.f, 0.f, 0.f);
}

// ---------------------------------------------------------------------------
// K3: edge phase. One thread per (edge, head). k|v fused gather (32B sector),
// vector atomics.
// ---------------------------------------------------------------------------
__global__ void __launch_bounds__(256) edge_kernel(
    const float4* __restrict__ edge_feat,
    const float*  __restrict__ radial,
    const int*    __restrict__ row,
    const int*    __restrict__ col)
{
    const int gid = blockIdx.x * blockDim.x + threadIdx.x;
    if (gid >= EE * HHH) return;
    const int e = gid >> 4;
    const int h = gid & 15;

    const int r = __ldcs(&row[e]);
    const int c = __ldcs(&col[e]);

    const float4 qv = __ldg(&g_q[r * 16 + h]);
    const float4 kv = __ldg(&g_kv[(c * 16 + h) * 2]);
    const float4 vv = __ldg(&g_kv[(c * 16 + h) * 2 + 1]);

    const float dot = qv.x * kv.x + qv.y * kv.y + qv.z * kv.z + qv.w * kv.w;

    // exact GELU: 0.5*x*(1+erf(x/sqrt(2)))
    const float attn = 0.5f * dot * (1.f + erff(dot * 0.70710678118654752f))
                     * __ldcs(&radial[e]);

    const float4 ef = __ldcs(&edge_feat[e * 16 + h]);

    float4* agg = &g_agg[r * 16 + h];
    asm volatile("red.global.add.v4.f32 [%0], {%1, %2, %3, %4};"
                 :: "l"(agg),
                    "f"(vv.x * ef.x * attn), "f"(vv.y * ef.y * attn),
                    "f"(vv.z * ef.z * attn), "f"(vv.w * ef.w * attn)
                 : "memory");
}

// ---------------------------------------------------------------------------
// K4: out = agg @ out_w + out_b ; result = dot * out[:, :64] + out[:, 64:]
// ---------------------------------------------------------------------------
__global__ void __launch_bounds__(128, 6) out_kernel(
    const float* __restrict__ out_w,
    const float* __restrict__ out_b,
    float* __restrict__ out)
{
    __shared__ __align__(16) ulonglong2 spw[16 * 128];   // 32 KB
    __shared__ __align__(16) float s_a[4][64];
    __shared__ __align__(16) float s_o[4][128];
    const int t = threadIdx.x;

#pragma unroll
    for (int kp = 0; kp < 16; kp++) {
        ulonglong2 p;
        p.x = pack2(out_w[(4 * kp    ) * 128 + t], out_w[(4 * kp + 1) * 128 + t]);
        p.y = pack2(out_w[(4 * kp + 2) * 128 + t], out_w[(4 * kp + 3) * 128 + t]);
        spw[kp * 128 + t] = p;
    }
    const float bc = out_b[t];
    __syncthreads();

    const float* agg = (const float*)g_agg;
    for (int it = 0; it < VEC_IT; it++) {
        const int n0 = (blockIdx.x + it * VEC_GRID) * 4;

        for (int i = t; i < 256; i += 128)
            ((float*)s_a)[i] = agg[n0 * 64 + i];
        __syncthreads();

        ull acc[4];
#pragma unroll
        for (int nd = 0; nd < 4; nd++) acc[nd] = 0;
        const ulonglong2* a4 = (const ulonglong2*)s_a;   // 16 per node
#pragma unroll
        for (int kp = 0; kp < 16; kp++) {
            const ulonglong2 w = spw[kp * 128 + t];
#pragma unroll
            for (int nd = 0; nd < 4; nd++) {
                const ulonglong2 v = a4[nd * 16 + kp];
                ffma2(acc[nd], v.x, w.x);
                ffma2(acc[nd], v.y, w.y);
            }
        }
#pragma unroll
        for (int nd = 0; nd < 4; nd++)
            s_o[nd][t] = sum2(acc[nd]) + bc;
        __syncthreads();

        if (t < 64) {
#pragma unroll
            for (int nd = 0; nd < 4; nd++)
                out[(n0 + nd) * 64 + t] =
                    g_dot[(n0 + nd) * 64 + t] * s_o[nd][t] + s_o[nd][64 + t];
        }
        __syncthreads();
    }
}

// ---------------------------------------------------------------------------
// Schedule (fork/join inside graph capture):
//   main stream : zero -> qkv -> edge -> (join) -> out
//   side stream : vec   (forked at entry; vec independent of zero/qkv/edge)
// out depends on edge (main) + vec (join event).
// Stream/events lazily created ONCE on the first (non-capturing) call.
// ---------------------------------------------------------------------------
extern "C" void kernel_launch(void* const* d_in, const int* in_sizes, int n_in,
                              void* d_out, int out_size)
{
    const float* node_feat = (const float*)d_in[0];
    const float* edge_feat = (const float*)d_in[1];
    const float* node_vec  = (const float*)d_in[2];
    const float* radial    = (const float*)d_in[3];
    const float* ln_g      = (const float*)d_in[4];
    const float* ln_b      = (const float*)d_in[5];
    const float* qkv_w     = (const float*)d_in[6];
    const float* qkv_b     = (const float*)d_in[7];
    const float* vec_w     = (const float*)d_in[8];
    const float* out_w     = (const float*)d_in[9];
    const float* out_b     = (const float*)d_in[10];
    const int*   row       = (const int*)d_in[11];
    const int*   col       = (const int*)d_in[12];
    float*       out       = (float*)d_out;

    static cudaStream_t s_side = nullptr;
    static cudaEvent_t  ev_fork = nullptr, ev_join = nullptr;
    if (s_side == nullptr) {
        cudaStreamCreateWithFlags(&s_side, cudaStreamNonBlocking);
        cudaEventCreateWithFlags(&ev_fork, cudaEventDisableTiming);
        cudaEventCreateWithFlags(&ev_join, cudaEventDisableTiming);
    }

    // fork: side stream branches off the capture (main) stream
    cudaEventRecord(ev_fork, 0);
    cudaStreamWaitEvent(s_side, ev_fork, 0);

    // side stream: vec (writes g_dot only)
    vec_kernel<<<VEC_GRID, 128, 0, s_side>>>(node_vec, vec_w);

    // main stream: zero -> qkv -> edge
    zero_kernel<<<(NN * HHH + 255) / 256, 256>>>();
    qkv_kernel<<<QKV_GRID, 192>>>(node_feat, ln_g, ln_b, qkv_w, qkv_b);
    edge_kernel<<<(EE * HHH + 255) / 256, 256>>>(
        (const float4*)edge_feat, radial, row, col);

    // join: out needs vec's g_dot and edge's g_agg
    cudaEventRecord(ev_join, s_side);
    cudaStreamWaitEvent(0, ev_join, 0);

    out_kernel<<<VEC_GRID, 128>>>(out_w, out_b, out);
}